// round 2
// baseline (speedup 1.0000x reference)
#include <cuda_runtime.h>
#include <math.h>

#define BB 8
#define SS 256
#define HH 100
#define PP 20
#define EPSF 1e-8f
#define NEGF 1e30f

// ---------------- scratch (static device globals; no runtime allocation) ----
__device__ float g_c[2][BB][SS][HH];        // masked contexts (0=p,1=h)
__device__ float g_norm[2][BB][SS];         // row L2 norms
__device__ float g_npw[2][BB][SS][4*PP];    // weighted row norms per weight-set
__device__ float g_w2[4][PP][HH];           // squared weights (full,maxpool,att,maxatt)
__device__ float g_last[2][BB][HH];         // last valid token rows
__device__ float g_nlast[2][BB];
__device__ float g_nlastw[2][BB][PP];       // w_full weighted norms of last rows
__device__ float g_len[2][BB];
__device__ float g_cos[BB][SS][SS];
__device__ float g_cosT[BB][SS][SS];
__device__ float g_cmax[2][BB][SS];
__device__ float g_cmean[2][BB][SS];
__device__ float g_csum[2][BB][SS];
__device__ float g_attmean[2][BB][SS][HH];
__device__ float g_attmax[2][BB][SS][HH];
__device__ float g_mpmax[2][BB][SS][PP];
__device__ float g_mpmean[2][BB][SS][PP];

// ---------------- K0: squared weights ---------------------------------------
__global__ void k_w2(const float* wf, const float* wm, const float* wa, const float* wx) {
    const float* w = (blockIdx.x == 0) ? wf : (blockIdx.x == 1) ? wm
                    : (blockIdx.x == 2) ? wa : wx;
    for (int idx = threadIdx.x; idx < PP * HH; idx += blockDim.x) {
        float v = w[idx];
        (&g_w2[blockIdx.x][0][0])[idx] = v * v;
    }
}

// ---------------- K1: mask, norms, weighted norms ----------------------------
__global__ void k_prep(const float* cp, const int* mp, const float* ch, const int* mh) {
    int side = blockIdx.y;
    int r = blockIdx.x, b = r / SS, i = r % SS;
    const float* ctx = side ? ch : cp;
    const int* msk = side ? mh : mp;
    int t = threadIdx.x;
    __shared__ float sx2[HH];
    float m = msk[r] ? 1.f : 0.f;
    if (t < HH) {
        float x = ctx[r * HH + t] * m;
        g_c[side][b][i][t] = x;
        sx2[t] = x * x;
    }
    __syncthreads();
    if (t < 4 * PP) {
        int ws = t / PP, p = t % PP;
        float s = 0.f;
        for (int h = 0; h < HH; h++) s += g_w2[ws][p][h] * sx2[h];
        g_npw[side][b][i][t] = sqrtf(s);
    }
    if (t == 96) {
        float s = 0.f;
        for (int h = 0; h < HH; h++) s += sx2[h];
        g_norm[side][b][i] = sqrtf(s);
    }
}

// ---------------- K2: lengths + last valid token -----------------------------
__global__ void k_last(const int* mp, const int* mh) {
    int side = blockIdx.y, b = blockIdx.x, t = threadIdx.x;
    const int* msk = side ? mh : mp;
    __shared__ int sred[128];
    __shared__ int sidx;
    int s = 0;
    for (int j = t; j < SS; j += 128) s += msk[b * SS + j];
    sred[t] = s;
    __syncthreads();
    if (t == 0) {
        int tot = 0;
        for (int k = 0; k < 128; k++) tot += sred[k];
        g_len[side][b] = (float)tot;
        sidx = (tot > 0) ? (tot - 1) : 0;
    }
    __syncthreads();
    int idx = sidx;
    if (t < HH) g_last[side][b][t] = g_c[side][b][idx][t];
    if (t < PP) g_nlastw[side][b][t] = g_npw[side][b][idx][t];  // w_full slot
    if (t == 127) g_nlast[side][b] = g_norm[side][b][idx];
}

// ---------------- K3: pairwise cosine (32x32 smem tiles) ---------------------
__global__ void k_cos() {
    int b = blockIdx.x, it = blockIdx.y, jt = blockIdx.z;
    __shared__ float sa[32][101], sb[32][101];
    __shared__ float sni[32], snj[32];
    int t = threadIdx.x;
    const float* ap = &g_c[0][b][it * 32][0];
    const float* bp = &g_c[1][b][jt * 32][0];
    for (int idx = t; idx < 32 * HH; idx += 256) {
        int r = idx / HH, h = idx % HH;
        sa[r][h] = ap[idx];
        sb[r][h] = bp[idx];
    }
    if (t < 32) {
        sni[t] = 1.f / fmaxf(g_norm[0][b][it * 32 + t], EPSF);
        snj[t] = 1.f / fmaxf(g_norm[1][b][jt * 32 + t], EPSF);
    }
    __syncthreads();
    int tx = t & 15, ty = t >> 4;
    float a00 = 0, a01 = 0, a10 = 0, a11 = 0;
    for (int h = 0; h < HH; h++) {
        float x0 = sa[ty * 2][h], x1 = sa[ty * 2 + 1][h];
        float y0 = sb[tx * 2][h], y1 = sb[tx * 2 + 1][h];
        a00 = fmaf(x0, y0, a00);
        a01 = fmaf(x0, y1, a01);
        a10 = fmaf(x1, y0, a10);
        a11 = fmaf(x1, y1, a11);
    }
    int i0 = it * 32 + ty * 2, j0 = jt * 32 + tx * 2;
    float c;
    c = a00 * sni[ty * 2] * snj[tx * 2];         g_cos[b][i0][j0] = c;     g_cosT[b][j0][i0] = c;
    c = a01 * sni[ty * 2] * snj[tx * 2 + 1];     g_cos[b][i0][j0 + 1] = c; g_cosT[b][j0 + 1][i0] = c;
    c = a10 * sni[ty * 2 + 1] * snj[tx * 2];     g_cos[b][i0 + 1][j0] = c; g_cosT[b][j0][i0 + 1] = c;
    c = a11 * sni[ty * 2 + 1] * snj[tx * 2 + 1]; g_cos[b][i0 + 1][j0 + 1] = c; g_cosT[b][j0 + 1][i0 + 1] = c;
}

// ---------------- K4: row reductions of cos (max / mean / sum) ---------------
__global__ void k_rowred(const int* mp, const int* mh) {
    int side = blockIdx.z, b = blockIdx.y, r = blockIdx.x, t = threadIdx.x;
    const float* row = side ? &g_cosT[b][r][0] : &g_cos[b][r][0];
    const int* omsk = side ? mp : mh;
    float v = row[t];
    float mv = omsk[b * SS + t] ? v : -NEGF;
    __shared__ float sm[256], ss[256];
    sm[t] = mv;
    ss[t] = v;
    __syncthreads();
    for (int o = 128; o; o >>= 1) {
        if (t < o) {
            sm[t] = fmaxf(sm[t], sm[t + o]);
            ss[t] += ss[t + o];
        }
        __syncthreads();
    }
    if (t == 0) {
        g_cmax[side][b][r] = sm[0];
        g_csum[side][b][r] = ss[0];
        g_cmean[side][b][r] = ss[0] / fmaxf(g_len[1 - side][b], EPSF);
    }
}

// ---------------- K5: attentive mean + max attentive vectors -----------------
__global__ void k_att(const int* mp, const int* mh) {
    int side = blockIdx.z, b = blockIdx.y, i = blockIdx.x, t = threadIdx.x;
    __shared__ float satt[SS];
    __shared__ float sbias[SS];
    const float* row = side ? &g_cosT[b][i][0] : &g_cos[b][i][0];
    const int* omsk = side ? mp : mh;
    for (int j = t; j < SS; j += 128) {
        satt[j] = row[j];
        sbias[j] = omsk[b * SS + j] ? 0.f : -NEGF;
    }
    __syncthreads();
    if (t < HH) {
        const float* oc = &g_c[1 - side][b][0][0];
        float mean = 0.f, vmax = -NEGF;
        for (int j = 0; j < SS; j++) {
            float prod = satt[j] * oc[j * HH + t];
            mean += prod;
            vmax = fmaxf(vmax, prod + sbias[j]);
        }
        float denom = fmaxf(g_csum[side][b][i], EPSF);
        g_attmean[side][b][i][t] = mean / denom;
        g_attmax[side][b][i][t] = vmax;
    }
}

// ---------------- K6: maxpool pairwise multi-perspective (dominant GEMM) -----
__global__ void k_maxpool(const int* mp, const int* mh) {
    int p = blockIdx.x, b = blockIdx.y;
    int t = threadIdx.x;                 // 256 threads, thread == row i
    __shared__ float w2s[HH];
    __shared__ float chs[32 * HH];
    __shared__ float sinvh[32];
    __shared__ float sbias[32];
    __shared__ float wmax[8][32];
    __shared__ float wsum[8][32];

    if (t < HH) w2s[t] = g_w2[1][p][t];
    int i = t;
    float nprow = g_npw[0][b][i][PP + p];
    int maski = mp[b * SS + i];
    float invp = (maski && nprow > 0.f) ? 1.f / nprow : 0.f;
    float len_p = g_len[0][b], len_h = g_len[1][b];

    float pmax = -NEGF, psum = 0.f;
    const float* cprow = &g_c[0][b][i][0];
    int lane = t & 31, w = t >> 5;

    for (int jt = 0; jt < 8; jt++) {
        __syncthreads();
        {
            const float* src = &g_c[1][b][jt * 32][0];
            for (int idx = t; idx < 32 * HH; idx += 256) chs[idx] = src[idx];
            if (t < 32) {
                int j = jt * 32 + t;
                float n = g_npw[1][b][j][PP + p];
                int mj = mh[b * SS + j];
                sinvh[t] = (mj && n > 0.f) ? 1.f / n : 0.f;
                sbias[t] = mj ? 0.f : -NEGF;
            }
        }
        __syncthreads();

        float dots[32];
#pragma unroll
        for (int jj = 0; jj < 32; jj++) dots[jj] = 0.f;
        for (int h = 0; h < HH; h++) {
            float a = cprow[h] * w2s[h];
#pragma unroll
            for (int jj = 0; jj < 32; jj++)
                dots[jj] = fmaf(a, chs[jj * HH + h], dots[jj]);
        }

#pragma unroll
        for (int jj = 0; jj < 32; jj++) {
            float d = dots[jj];
            float v = d * sinvh[jj];          // 0 at masked j
            psum += v;
            pmax = fmaxf(pmax, v + sbias[jj]);
            float u = d * invp;               // 0 at masked i
            float um = maski ? u : -NEGF;
#pragma unroll
            for (int o = 16; o; o >>= 1) {
                um = fmaxf(um, __shfl_xor_sync(0xffffffffu, um, o));
                u += __shfl_xor_sync(0xffffffffu, u, o);
            }
            if (lane == 0) { wmax[w][jj] = um; wsum[w][jj] = u; }
        }
        __syncthreads();
        if (t < 32) {
            int j = jt * 32 + t;
            float hm = -NEGF, hs = 0.f;
#pragma unroll
            for (int ww = 0; ww < 8; ww++) {
                hm = fmaxf(hm, wmax[ww][t]);
                hs += wsum[ww][t];
            }
            g_mpmax[1][b][j][p] = hm * sinvh[t];
            g_mpmean[1][b][j][p] = hs * sinvh[t] / fmaxf(len_p, EPSF);
        }
    }
    g_mpmax[0][b][i][p] = pmax * invp;
    g_mpmean[0][b][i][p] = psum * invp / fmaxf(len_h, EPSF);
}

// ---------------- K7: assemble 105 outputs per (side,b,i) --------------------
__global__ void k_final(float* out) {
    int side = blockIdx.z, b = blockIdx.y, i = blockIdx.x, t = threadIdx.x;
    __shared__ float sx[HH], sL[HH], sva[HH], svm[HH], sred[105];
    if (t < HH) {
        sx[t] = g_c[side][b][i][t];
        sL[t] = g_last[1 - side][b][t];
        sva[t] = g_attmean[side][b][i][t];
        svm[t] = g_attmax[side][b][i][t];
    }
    __syncthreads();
    if (t < 105) {
        float s = 0.f;
        if (t == 0)      { for (int h = 0; h < HH; h++) s += sx[h] * sL[h]; }
        else if (t == 1) { for (int h = 0; h < HH; h++) s += sx[h] * sva[h]; }
        else if (t == 2) { for (int h = 0; h < HH; h++) s += sx[h] * svm[h]; }
        else if (t == 3) { for (int h = 0; h < HH; h++) s += sva[h] * sva[h]; }
        else if (t == 4) { for (int h = 0; h < HH; h++) s += svm[h] * svm[h]; }
        else if (t < 25) { int p = t - 5;  for (int h = 0; h < HH; h++) s += g_w2[0][p][h] * sx[h] * sL[h]; }
        else if (t < 45) { int p = t - 25; for (int h = 0; h < HH; h++) s += g_w2[2][p][h] * sx[h] * sva[h]; }
        else if (t < 65) { int p = t - 45; for (int h = 0; h < HH; h++) s += g_w2[2][p][h] * sva[h] * sva[h]; }
        else if (t < 85) { int p = t - 65; for (int h = 0; h < HH; h++) s += g_w2[3][p][h] * sx[h] * svm[h]; }
        else             { int p = t - 85; for (int h = 0; h < HH; h++) s += g_w2[3][p][h] * svm[h] * svm[h]; }
        sred[t] = s;
    }
    __syncthreads();
    if (t < 105) {
        float np = g_norm[side][b][i];
        float o;
        if (t == 0)      o = g_cmax[side][b][i];
        else if (t == 1) o = g_cmean[side][b][i];
        else if (t == 2) o = sred[0] / (fmaxf(np, EPSF) * fmaxf(g_nlast[1 - side][b], EPSF));
        else if (t < 23) {
            int p = t - 3;
            o = sred[5 + p] / (fmaxf(g_npw[side][b][i][p], EPSF) * fmaxf(g_nlastw[1 - side][b][p], EPSF));
        }
        else if (t < 43) o = g_mpmax[side][b][i][t - 23];
        else if (t < 63) o = g_mpmean[side][b][i][t - 43];
        else if (t == 63) o = sred[1] / (fmaxf(np, EPSF) * fmaxf(sqrtf(sred[3]), EPSF));
        else if (t < 84) {
            int p = t - 64;
            o = sred[25 + p] / (fmaxf(g_npw[side][b][i][2 * PP + p], EPSF) * fmaxf(sqrtf(sred[45 + p]), EPSF));
        }
        else if (t == 84) o = sred[2] / (fmaxf(np, EPSF) * fmaxf(sqrtf(sred[4]), EPSF));
        else {
            int p = t - 85;
            o = sred[65 + p] / (fmaxf(g_npw[side][b][i][3 * PP + p], EPSF) * fmaxf(sqrtf(sred[85 + p]), EPSF));
        }
        out[((size_t)(side * BB + b) * SS + i) * 105 + t] = o;
    }
}

// ---------------- launch ------------------------------------------------------
extern "C" void kernel_launch(void* const* d_in, const int* in_sizes, int n_in,
                              void* d_out, int out_size) {
    const float* ctx_p = (const float*)d_in[0];
    const int*   mp    = (const int*)d_in[1];
    const float* ctx_h = (const float*)d_in[2];
    const int*   mh    = (const int*)d_in[3];
    const float* wf    = (const float*)d_in[4];
    const float* wm    = (const float*)d_in[5];
    const float* wa    = (const float*)d_in[6];
    const float* wx    = (const float*)d_in[7];
    float* out = (float*)d_out;

    k_w2<<<4, 256>>>(wf, wm, wa, wx);
    k_prep<<<dim3(BB * SS, 2), 128>>>(ctx_p, mp, ctx_h, mh);
    k_last<<<dim3(BB, 2), 128>>>(mp, mh);
    k_cos<<<dim3(BB, 8, 8), 256>>>();
    k_rowred<<<dim3(SS, BB, 2), 256>>>(mp, mh);
    k_att<<<dim3(SS, BB, 2), 128>>>(mp, mh);
    k_maxpool<<<dim3(PP, BB), 256>>>(mp, mh);
    k_final<<<dim3(SS, BB, 2), 128>>>(out);
}

// round 6
// speedup vs baseline: 1.3722x; 1.3722x over previous
#include <cuda_runtime.h>
#include <math.h>

#define BB 8
#define SS 256
#define HH 100
#define PP 20
#define EPSF 1e-8f
#define NEGF 1e30f
typedef unsigned long long ull;

__device__ __forceinline__ ull pk2(float lo, float hi) {
    ull r; asm("mov.b64 %0, {%1,%2};" : "=l"(r) : "f"(lo), "f"(hi)); return r;
}
__device__ __forceinline__ void unpk2(ull v, float& lo, float& hi) {
    asm("mov.b64 {%0,%1}, %2;" : "=f"(lo), "=f"(hi) : "l"(v));
}
__device__ __forceinline__ ull fma2_(ull a, ull b, ull c) {
    ull d; asm("fma.rn.f32x2 %0, %1, %2, %3;" : "=l"(d) : "l"(a), "l"(b), "l"(c)); return d;
}

// ---------------- scratch -----------------------------------------------------
__device__ float g_c[2][BB][SS][HH];
__device__ float g_cT[2][BB][HH][SS];       // h-major copy
__device__ float g_norm[2][BB][SS];
__device__ float g_npw[2][BB][SS][4 * PP];
__device__ float g_w2[4][PP][HH];
__device__ float g_last[2][BB][HH];
__device__ float g_nlast[2][BB];
__device__ float g_nlastw[2][BB][PP];
__device__ float g_len[2][BB];
__device__ float g_cos[BB][SS][SS];
__device__ float g_cosT[BB][SS][SS];
__device__ float g_cmax[2][BB][SS];
__device__ float g_cmean[2][BB][SS];
__device__ float g_csum[2][BB][SS];
__device__ float g_attmean[2][BB][SS][HH];
__device__ float g_attmax[2][BB][SS][HH];
__device__ float g_mpmax[2][BB][SS][PP];
__device__ float g_mpmean[2][BB][SS][PP];
__device__ float g_colmax[4][BB][PP][SS];
__device__ float g_colsum[4][BB][PP][SS];

// ---------------- K0 ----------------------------------------------------------
__global__ void k_w2(const float* wf, const float* wm, const float* wa, const float* wx) {
    const float* w = (blockIdx.x == 0) ? wf : (blockIdx.x == 1) ? wm
                    : (blockIdx.x == 2) ? wa : wx;
    for (int idx = threadIdx.x; idx < PP * HH; idx += blockDim.x) {
        float v = w[idx];
        (&g_w2[blockIdx.x][0][0])[idx] = v * v;
    }
}

// ---------------- K1: mask, norms, weighted norms, transpose ------------------
__global__ void k_prep(const float* cp, const int* mp, const float* ch, const int* mh) {
    int side = blockIdx.y;
    int r = blockIdx.x, b = r / SS, i = r % SS;
    const float* ctx = side ? ch : cp;
    const int* msk = side ? mh : mp;
    int t = threadIdx.x;
    __shared__ float sx2[HH];
    float m = msk[r] ? 1.f : 0.f;
    if (t < HH) {
        float x = ctx[r * HH + t] * m;
        g_c[side][b][i][t] = x;
        g_cT[side][b][t][i] = x;
        sx2[t] = x * x;
    }
    __syncthreads();
    if (t < 4 * PP) {
        int ws = t / PP, p = t % PP;
        float s = 0.f;
        for (int h = 0; h < HH; h++) s += g_w2[ws][p][h] * sx2[h];
        g_npw[side][b][i][t] = sqrtf(s);
    }
    if (t == 96) {
        float s = 0.f;
        for (int h = 0; h < HH; h++) s += sx2[h];
        g_norm[side][b][i] = sqrtf(s);
    }
}

// ---------------- K2: lengths + last valid token ------------------------------
__global__ void k_last(const int* mp, const int* mh) {
    int side = blockIdx.y, b = blockIdx.x, t = threadIdx.x;
    const int* msk = side ? mh : mp;
    __shared__ int sred[128];
    __shared__ int sidx;
    int s = 0;
    for (int j = t; j < SS; j += 128) s += msk[b * SS + j];
    sred[t] = s;
    __syncthreads();
    if (t == 0) {
        int tot = 0;
        for (int k = 0; k < 128; k++) tot += sred[k];
        g_len[side][b] = (float)tot;
        sidx = (tot > 0) ? (tot - 1) : 0;
    }
    __syncthreads();
    int idx = sidx;
    if (t < HH) g_last[side][b][t] = g_c[side][b][idx][t];
    if (t < PP) g_nlastw[side][b][t] = g_npw[side][b][idx][t];
    if (t == 127) g_nlast[side][b] = g_norm[side][b][idx];
}

// ---------------- K3: pairwise cosine GEMM (f32x2, 64x32 tile) ----------------
__global__ void k_cos() {
    int b = blockIdx.x, i0 = blockIdx.y * 64, j0 = blockIdx.z * 32;
    int t = threadIdx.x, tx = t & 15, ty = t >> 4;
    __shared__ ull sA[HH][34];   // i-pairs (EVEN pad: 16B alignment for all h)
    __shared__ ull sB[HH][18];   // j-pairs (EVEN pad)
    __shared__ float sni[64], snj[32];
    for (int idx = t; idx < HH * 32; idx += 256) {
        int h = idx >> 5, ip = idx & 31;
        float2 v = *(const float2*)&g_cT[0][b][h][i0 + 2 * ip];
        sA[h][ip] = pk2(v.x, v.y);
    }
    for (int idx = t; idx < HH * 16; idx += 256) {
        int h = idx >> 4, jp = idx & 15;
        float2 v = *(const float2*)&g_cT[1][b][h][j0 + 2 * jp];
        sB[h][jp] = pk2(v.x, v.y);
    }
    if (t < 64) sni[t] = 1.f / fmaxf(g_norm[0][b][i0 + t], EPSF);
    if (t < 32) snj[t] = 1.f / fmaxf(g_norm[1][b][j0 + t], EPSF);
    __syncthreads();
    ull a00 = 0, a01 = 0, a10 = 0, a11 = 0;
    for (int h = 0; h < HH; h++) {
        ulonglong2 a = *(const ulonglong2*)&sA[h][ty * 2];
        ull bp = sB[h][tx];
        float bl, bh; unpk2(bp, bl, bh);
        ull d0 = pk2(bl, bl), d1 = pk2(bh, bh);
        a00 = fma2_(a.x, d0, a00); a01 = fma2_(a.y, d0, a01);
        a10 = fma2_(a.x, d1, a10); a11 = fma2_(a.y, d1, a11);
    }
    float d[2][4];
    unpk2(a00, d[0][0], d[0][1]); unpk2(a01, d[0][2], d[0][3]);
    unpk2(a10, d[1][0], d[1][1]); unpk2(a11, d[1][2], d[1][3]);
#pragma unroll
    for (int jj = 0; jj < 2; jj++) {
        int j = j0 + tx * 2 + jj;
        float fj = snj[tx * 2 + jj];
#pragma unroll
        for (int r = 0; r < 4; r++) {
            int i = i0 + ty * 4 + r;
            float v = d[jj][r] * sni[ty * 4 + r] * fj;
            g_cos[b][i][j] = v;
            g_cosT[b][j][i] = v;
        }
    }
}

// ---------------- K4: row reductions of cos -----------------------------------
__global__ void k_rowred(const int* mp, const int* mh) {
    int side = blockIdx.z, b = blockIdx.y, r = blockIdx.x, t = threadIdx.x;
    const float* row = side ? &g_cosT[b][r][0] : &g_cos[b][r][0];
    const int* omsk = side ? mp : mh;
    float v = row[t];
    float mv = omsk[b * SS + t] ? v : -NEGF;
    __shared__ float sm[256], ss[256];
    sm[t] = mv; ss[t] = v;
    __syncthreads();
    for (int o = 128; o; o >>= 1) {
        if (t < o) { sm[t] = fmaxf(sm[t], sm[t + o]); ss[t] += ss[t + o]; }
        __syncthreads();
    }
    if (t == 0) {
        g_cmax[side][b][r] = sm[0];
        g_csum[side][b][r] = ss[0];
        g_cmean[side][b][r] = ss[0] / fmaxf(g_len[1 - side][b], EPSF);
    }
}

// ---------------- K5: attentive mean + max (fused, float4 stream) -------------
__global__ void k_att(const int* mp, const int* mh) {
    int i = blockIdx.x, b = blockIdx.y, side = blockIdx.z;
    int t = threadIdx.x;
    __shared__ float4 satt[64], sbias[64];
    const float* row = side ? &g_cosT[b][i][0] : &g_cos[b][i][0];
    const int* omsk = side ? mp : mh;
    for (int j = t; j < SS; j += 128) {
        ((float*)satt)[j] = row[j];
        ((float*)sbias)[j] = omsk[b * SS + j] ? 0.f : -NEGF;
    }
    __syncthreads();
    if (t < HH) {
        const float4* oc = (const float4*)&g_cT[1 - side][b][t][0];
        float mean = 0.f, vmax = -NEGF;
#pragma unroll 4
        for (int q = 0; q < 64; q++) {
            float4 v = oc[q], a = satt[q], bv = sbias[q];
            mean = fmaf(a.x, v.x, mean); vmax = fmaxf(vmax, fmaf(a.x, v.x, bv.x));
            mean = fmaf(a.y, v.y, mean); vmax = fmaxf(vmax, fmaf(a.y, v.y, bv.y));
            mean = fmaf(a.z, v.z, mean); vmax = fmaxf(vmax, fmaf(a.z, v.z, bv.z));
            mean = fmaf(a.w, v.w, mean); vmax = fmaxf(vmax, fmaf(a.w, v.w, bv.w));
        }
        float denom = fmaxf(g_csum[side][b][i], EPSF);
        g_attmean[side][b][i][t] = mean / denom;
        g_attmax[side][b][i][t] = vmax;
    }
}

// ---------------- K6: maxpool multi-perspective GEMM (f32x2) ------------------
// grid (PP, BB, 4); block 128 = tx8 x ty16; i-tile 64, 8 j-tiles of 32
__global__ void __launch_bounds__(128) k_maxpool(const int* mp, const int* mh) {
    int p = blockIdx.x, b = blockIdx.y, ibl = blockIdx.z, i0 = ibl * 64;
    int t = threadIdx.x, tx = t & 7, ty = t >> 3;
    __shared__ ull sA[HH][34];          // premultiplied i-pairs (EVEN pad)
    __shared__ ull sB[HH][18];          // j-pairs (EVEN pad)
    __shared__ float sRedM[16][32], sRedS[16][32];
    __shared__ float sbJ[32], siJ[32];

    for (int idx = t; idx < HH * 32; idx += 128) {
        int h = idx >> 5, ip = idx & 31;
        float2 v = *(const float2*)&g_cT[0][b][h][i0 + 2 * ip];
        float w = g_w2[1][p][h];
        sA[h][ip] = pk2(v.x * w, v.y * w);
    }
    float invp[4], biasI[4], pmax[4], psum[4];
#pragma unroll
    for (int r = 0; r < 4; r++) {
        int i = i0 + ty * 4 + r;
        float n = g_npw[0][b][i][PP + p];
        int mi = mp[b * SS + i];
        invp[r] = (mi && n > 0.f) ? 1.f / n : 0.f;
        biasI[r] = mi ? 0.f : -NEGF;
        pmax[r] = -NEGF; psum[r] = 0.f;
    }
    float len_h = g_len[1][b];

    for (int jt = 0; jt < 8; jt++) {
        int j0 = jt * 32;
        __syncthreads();
        for (int idx = t; idx < HH * 16; idx += 128) {
            int h = idx >> 4, jp = idx & 15;
            float2 v = *(const float2*)&g_cT[1][b][h][j0 + 2 * jp];
            sB[h][jp] = pk2(v.x, v.y);
        }
        if (t < 32) {
            int j = j0 + t;
            float n = g_npw[1][b][j][PP + p];
            int mj = mh[b * SS + j];
            siJ[t] = (mj && n > 0.f) ? 1.f / n : 0.f;
            sbJ[t] = mj ? 0.f : -NEGF;
        }
        __syncthreads();

        ull acc[4][2];
#pragma unroll
        for (int jj = 0; jj < 4; jj++) { acc[jj][0] = 0; acc[jj][1] = 0; }
#pragma unroll 4
        for (int h = 0; h < HH; h++) {
            ulonglong2 a = *(const ulonglong2*)&sA[h][ty * 2];
            ulonglong2 bp = *(const ulonglong2*)&sB[h][tx * 2];
            float b0, b1, b2, b3;
            unpk2(bp.x, b0, b1); unpk2(bp.y, b2, b3);
            ull d0 = pk2(b0, b0), d1 = pk2(b1, b1), d2 = pk2(b2, b2), d3 = pk2(b3, b3);
            acc[0][0] = fma2_(a.x, d0, acc[0][0]); acc[0][1] = fma2_(a.y, d0, acc[0][1]);
            acc[1][0] = fma2_(a.x, d1, acc[1][0]); acc[1][1] = fma2_(a.y, d1, acc[1][1]);
            acc[2][0] = fma2_(a.x, d2, acc[2][0]); acc[2][1] = fma2_(a.y, d2, acc[2][1]);
            acc[3][0] = fma2_(a.x, d3, acc[3][0]); acc[3][1] = fma2_(a.y, d3, acc[3][1]);
        }
#pragma unroll
        for (int jj = 0; jj < 4; jj++) {
            int jl = tx * 4 + jj;
            float sj = siJ[jl], bj = sbJ[jl];
            float cm = -NEGF, cs = 0.f;
#pragma unroll
            for (int rp = 0; rp < 2; rp++) {
                float dl, dh; unpk2(acc[jj][rp], dl, dh);
                int r0 = rp * 2, r1 = rp * 2 + 1;
                float v0 = dl * sj; psum[r0] += v0; pmax[r0] = fmaxf(pmax[r0], v0 + bj);
                float v1 = dh * sj; psum[r1] += v1; pmax[r1] = fmaxf(pmax[r1], v1 + bj);
                float u0 = dl * invp[r0]; cs += u0; cm = fmaxf(cm, u0 + biasI[r0]);
                float u1 = dh * invp[r1]; cs += u1; cm = fmaxf(cm, u1 + biasI[r1]);
            }
            sRedM[ty][jl] = cm; sRedS[ty][jl] = cs;
        }
        __syncthreads();
        if (t < 32) {
            float m = -NEGF, s = 0.f;
#pragma unroll
            for (int k = 0; k < 16; k++) { m = fmaxf(m, sRedM[k][t]); s += sRedS[k][t]; }
            g_colmax[ibl][b][p][j0 + t] = m;
            g_colsum[ibl][b][p][j0 + t] = s;
        }
    }
#pragma unroll
    for (int r = 0; r < 4; r++) {
        float m = pmax[r], s = psum[r];
        for (int o = 4; o; o >>= 1) {
            m = fmaxf(m, __shfl_xor_sync(0xffffffffu, m, o));
            s += __shfl_xor_sync(0xffffffffu, s, o);
        }
        if (tx == 0) {
            int i = i0 + ty * 4 + r;
            g_mpmax[0][b][i][p] = m * invp[r];
            g_mpmean[0][b][i][p] = s * invp[r] / fmaxf(len_h, EPSF);
        }
    }
}

// ---------------- K6b: combine column partials --------------------------------
__global__ void k_mpc(const int* mh) {
    int p = blockIdx.x, b = blockIdx.y, j = threadIdx.x;
    float m = -NEGF, s = 0.f;
#pragma unroll
    for (int k = 0; k < 4; k++) {
        m = fmaxf(m, g_colmax[k][b][p][j]);
        s += g_colsum[k][b][p][j];
    }
    float n = g_npw[1][b][j][PP + p];
    int mj = mh[b * SS + j];
    float inv = (mj && n > 0.f) ? 1.f / n : 0.f;
    g_mpmax[1][b][j][p] = m * inv;
    g_mpmean[1][b][j][p] = s * inv / fmaxf(g_len[0][b], EPSF);
}

// ---------------- K7: assemble 105 outputs ------------------------------------
__global__ void k_final(float* out) {
    int side = blockIdx.z, b = blockIdx.y, i = blockIdx.x, t = threadIdx.x;
    __shared__ float sx[HH], sL[HH], sva[HH], svm[HH], sred[105];
    if (t < HH) {
        sx[t] = g_c[side][b][i][t];
        sL[t] = g_last[1 - side][b][t];
        sva[t] = g_attmean[side][b][i][t];
        svm[t] = g_attmax[side][b][i][t];
    }
    __syncthreads();
    if (t < 105) {
        float s = 0.f;
        if (t == 0)      { for (int h = 0; h < HH; h++) s += sx[h] * sL[h]; }
        else if (t == 1) { for (int h = 0; h < HH; h++) s += sx[h] * sva[h]; }
        else if (t == 2) { for (int h = 0; h < HH; h++) s += sx[h] * svm[h]; }
        else if (t == 3) { for (int h = 0; h < HH; h++) s += sva[h] * sva[h]; }
        else if (t == 4) { for (int h = 0; h < HH; h++) s += svm[h] * svm[h]; }
        else if (t < 25) { int p = t - 5;  for (int h = 0; h < HH; h++) s += g_w2[0][p][h] * sx[h] * sL[h]; }
        else if (t < 45) { int p = t - 25; for (int h = 0; h < HH; h++) s += g_w2[2][p][h] * sx[h] * sva[h]; }
        else if (t < 65) { int p = t - 45; for (int h = 0; h < HH; h++) s += g_w2[2][p][h] * sva[h] * sva[h]; }
        else if (t < 85) { int p = t - 65; for (int h = 0; h < HH; h++) s += g_w2[3][p][h] * sx[h] * svm[h]; }
        else             { int p = t - 85; for (int h = 0; h < HH; h++) s += g_w2[3][p][h] * svm[h] * svm[h]; }
        sred[t] = s;
    }
    __syncthreads();
    if (t < 105) {
        float np = g_norm[side][b][i];
        float o;
        if (t == 0)      o = g_cmax[side][b][i];
        else if (t == 1) o = g_cmean[side][b][i];
        else if (t == 2) o = sred[0] / (fmaxf(np, EPSF) * fmaxf(g_nlast[1 - side][b], EPSF));
        else if (t < 23) {
            int p = t - 3;
            o = sred[5 + p] / (fmaxf(g_npw[side][b][i][p], EPSF) * fmaxf(g_nlastw[1 - side][b][p], EPSF));
        }
        else if (t < 43) o = g_mpmax[side][b][i][t - 23];
        else if (t < 63) o = g_mpmean[side][b][i][t - 43];
        else if (t == 63) o = sred[1] / (fmaxf(np, EPSF) * fmaxf(sqrtf(sred[3]), EPSF));
        else if (t < 84) {
            int p = t - 64;
            o = sred[25 + p] / (fmaxf(g_npw[side][b][i][2 * PP + p], EPSF) * fmaxf(sqrtf(sred[45 + p]), EPSF));
        }
        else if (t == 84) o = sred[2] / (fmaxf(np, EPSF) * fmaxf(sqrtf(sred[4]), EPSF));
        else {
            int p = t - 85;
            o = sred[65 + p] / (fmaxf(g_npw[side][b][i][3 * PP + p], EPSF) * fmaxf(sqrtf(sred[85 + p]), EPSF));
        }
        out[((size_t)(side * BB + b) * SS + i) * 105 + t] = o;
    }
}

// ---------------- launch ------------------------------------------------------
extern "C" void kernel_launch(void* const* d_in, const int* in_sizes, int n_in,
                              void* d_out, int out_size) {
    const float* ctx_p = (const float*)d_in[0];
    const int*   mp    = (const int*)d_in[1];
    const float* ctx_h = (const float*)d_in[2];
    const int*   mh    = (const int*)d_in[3];
    const float* wf    = (const float*)d_in[4];
    const float* wm    = (const float*)d_in[5];
    const float* wa    = (const float*)d_in[6];
    const float* wx    = (const float*)d_in[7];
    float* out = (float*)d_out;

    k_w2<<<4, 256>>>(wf, wm, wa, wx);
    k_prep<<<dim3(BB * SS, 2), 128>>>(ctx_p, mp, ctx_h, mh);
    k_last<<<dim3(BB, 2), 128>>>(mp, mh);
    k_cos<<<dim3(BB, 4, 8), 256>>>();
    k_rowred<<<dim3(SS, BB, 2), 256>>>(mp, mh);
    k_att<<<dim3(SS, BB, 2), 128>>>(mp, mh);
    k_maxpool<<<dim3(PP, BB, 4), 128>>>(mp, mh);
    k_mpc<<<dim3(PP, BB), 256>>>(mh);
    k_final<<<dim3(SS, BB, 2), 128>>>(out);
}

// round 7
// speedup vs baseline: 1.7559x; 1.2796x over previous
#include <cuda_runtime.h>
#include <math.h>

#define BB 8
#define SS 256
#define HH 100
#define PP 20
#define EPSF 1e-8f
#define NEGF 1e30f
typedef unsigned long long ull;

__device__ __forceinline__ ull pk2(float lo, float hi) {
    ull r; asm("mov.b64 %0, {%1,%2};" : "=l"(r) : "f"(lo), "f"(hi)); return r;
}
__device__ __forceinline__ void unpk2(ull v, float& lo, float& hi) {
    asm("mov.b64 {%0,%1}, %2;" : "=f"(lo), "=f"(hi) : "l"(v));
}
__device__ __forceinline__ ull fma2_(ull a, ull b, ull c) {
    ull d; asm("fma.rn.f32x2 %0, %1, %2, %3;" : "=l"(d) : "l"(a), "l"(b), "l"(c)); return d;
}

// ---------------- scratch -----------------------------------------------------
__device__ float g_c[2][BB][SS][HH];
__device__ float g_cT[2][BB][HH][SS];
__device__ float g_norm[2][BB][SS];
__device__ float g_npw[2][BB][SS][4 * PP];
__device__ float g_w2[4][PP][HH];
__device__ float g_last[2][BB][HH];
__device__ float g_nlast[2][BB];
__device__ float g_nlastw[2][BB][PP];
__device__ float g_len[2][BB];
__device__ float g_cos[BB][SS][SS];
__device__ float g_cosT[BB][SS][SS];
__device__ float g_cmax[2][BB][SS];
__device__ float g_cmean[2][BB][SS];
__device__ float g_csum[2][BB][SS];
__device__ float g_attmean[2][BB][SS][HH];
__device__ float g_attmax[2][BB][SS][HH];
__device__ float g_mpmax[2][BB][SS][PP];
__device__ float g_mpmean[2][BB][SS][PP];
__device__ float g_colmax[4][BB][PP][SS];
__device__ float g_colsum[4][BB][PP][SS];

// ---------------- K0: squared weights -----------------------------------------
__global__ void k_w2(const float* wf, const float* wm, const float* wa, const float* wx) {
    const float* w = (blockIdx.x == 0) ? wf : (blockIdx.x == 1) ? wm
                    : (blockIdx.x == 2) ? wa : wx;
    for (int idx = threadIdx.x; idx < PP * HH; idx += blockDim.x) {
        float v = w[idx];
        (&g_w2[blockIdx.x][0][0])[idx] = v * v;
    }
}

// ---------------- K1a: mask + transpose + plain norms (coalesced) -------------
__global__ void k_prep1(const float* cp, const int* mp, const float* ch, const int* mh) {
    int side = blockIdx.y, r = blockIdx.x, b = r / SS, i = r % SS;
    const float* ctx = side ? ch : cp;
    const int* msk = side ? mh : mp;
    int t = threadIdx.x;
    float m = msk[r] ? 1.f : 0.f;
    float x = 0.f;
    if (t < HH) {
        x = ctx[r * HH + t] * m;
        g_c[side][b][i][t] = x;
        g_cT[side][b][t][i] = x;
    }
    float s = x * x;
    __shared__ float sw[4];
    for (int o = 16; o; o >>= 1) s += __shfl_xor_sync(0xffffffffu, s, o);
    if ((t & 31) == 0) sw[t >> 5] = s;
    __syncthreads();
    if (t == 0) g_norm[side][b][i] = sqrtf(sw[0] + sw[1] + sw[2] + sw[3]);
}

// ---------------- K1b: weighted norms (tiled smem matmul) ---------------------
// grid (16, BB, 2); block 128; 16 rows per block, 80 weighted norms each
__global__ void __launch_bounds__(128) k_prep2() {
    int gq = blockIdx.x, b = blockIdx.y, side = blockIdx.z;
    int i0 = gq * 16, t = threadIdx.x;
    __shared__ float sW[80][101];
    __shared__ float sX[16][101];
    const float* w2f = &g_w2[0][0][0];
    for (int idx = t; idx < 80 * HH; idx += 128) {
        int pr = idx / HH, h = idx % HH;
        sW[pr][h] = w2f[idx];
    }
    for (int idx = t; idx < 16 * HH; idx += 128) {
        int r = idx / HH, h = idx % HH;
        float x = g_c[side][b][i0 + r][h];
        sX[r][h] = x * x;
    }
    __syncthreads();
    for (int o = t; o < 1280; o += 128) {
        int pr = o % 80, r = o / 80;
        float s = 0.f;
#pragma unroll 4
        for (int h = 0; h < HH; h++) s += sW[pr][h] * sX[r][h];
        g_npw[side][b][i0 + r][pr] = sqrtf(s);
    }
}

// ---------------- K2: lengths + last valid token ------------------------------
__global__ void k_last(const int* mp, const int* mh) {
    int side = blockIdx.y, b = blockIdx.x, t = threadIdx.x;
    const int* msk = side ? mh : mp;
    __shared__ int sred[128];
    __shared__ int sidx;
    int s = 0;
    for (int j = t; j < SS; j += 128) s += msk[b * SS + j];
    sred[t] = s;
    __syncthreads();
    if (t == 0) {
        int tot = 0;
        for (int k = 0; k < 128; k++) tot += sred[k];
        g_len[side][b] = (float)tot;
        sidx = (tot > 0) ? (tot - 1) : 0;
    }
    __syncthreads();
    int idx = sidx;
    if (t < HH) g_last[side][b][t] = g_c[side][b][idx][t];
    if (t < PP) g_nlastw[side][b][t] = g_npw[side][b][idx][t];
    if (t == 127) g_nlast[side][b] = g_norm[side][b][idx];
}

// ---------------- K3: pairwise cosine GEMM (f32x2, 64x16, dup-B) --------------
// grid (BB, 4, 16); block 128 = tx8 x ty16; micro 4i x 2j
__global__ void __launch_bounds__(128) k_cos() {
    int b = blockIdx.x, i0 = blockIdx.y * 64, j0 = blockIdx.z * 16;
    int t = threadIdx.x, tx = t & 7, ty = t >> 3;
    __shared__ ull sA[HH][34];
    __shared__ ull sBd[HH][18];
    __shared__ float sni[64], snj[16];
    for (int idx = t; idx < HH * 32; idx += 128) {
        int h = idx >> 5, ip = idx & 31;
        float2 v = *(const float2*)&g_cT[0][b][h][i0 + 2 * ip];
        sA[h][ip] = pk2(v.x, v.y);
    }
    for (int idx = t; idx < HH * 16; idx += 128) {
        int h = idx >> 4, j = idx & 15;
        float v = g_cT[1][b][h][j0 + j];
        sBd[h][j] = pk2(v, v);
    }
    if (t < 64) sni[t] = 1.f / fmaxf(g_norm[0][b][i0 + t], EPSF);
    if (t < 16) snj[t] = 1.f / fmaxf(g_norm[1][b][j0 + t], EPSF);
    __syncthreads();
    ull acc[2][2] = {0, 0, 0, 0};
#pragma unroll 4
    for (int h = 0; h < HH; h++) {
        ulonglong2 a = *(const ulonglong2*)&sA[h][ty * 2];
        ulonglong2 bd = *(const ulonglong2*)&sBd[h][tx * 2];
        acc[0][0] = fma2_(a.x, bd.x, acc[0][0]);
        acc[0][1] = fma2_(a.y, bd.x, acc[0][1]);
        acc[1][0] = fma2_(a.x, bd.y, acc[1][0]);
        acc[1][1] = fma2_(a.y, bd.y, acc[1][1]);
    }
#pragma unroll
    for (int jj = 0; jj < 2; jj++) {
        int j = j0 + tx * 2 + jj;
        float fj = snj[tx * 2 + jj];
#pragma unroll
        for (int rp = 0; rp < 2; rp++) {
            float dl, dh; unpk2(acc[jj][rp], dl, dh);
            int i = i0 + ty * 4 + rp * 2;
            float v0 = dl * sni[ty * 4 + rp * 2] * fj;
            float v1 = dh * sni[ty * 4 + rp * 2 + 1] * fj;
            g_cos[b][i][j] = v0;     g_cosT[b][j][i] = v0;
            g_cos[b][i + 1][j] = v1; g_cosT[b][j][i + 1] = v1;
        }
    }
}

// ---------------- K4: row reductions of cos -----------------------------------
__global__ void k_rowred(const int* mp, const int* mh) {
    int side = blockIdx.z, b = blockIdx.y, r = blockIdx.x, t = threadIdx.x;
    const float* row = side ? &g_cosT[b][r][0] : &g_cos[b][r][0];
    const int* omsk = side ? mp : mh;
    float v = row[t];
    float mv = omsk[b * SS + t] ? v : -NEGF;
    __shared__ float sm[256], ss[256];
    sm[t] = mv; ss[t] = v;
    __syncthreads();
    for (int o = 128; o; o >>= 1) {
        if (t < o) { sm[t] = fmaxf(sm[t], sm[t + o]); ss[t] += ss[t + o]; }
        __syncthreads();
    }
    if (t == 0) {
        g_cmax[side][b][r] = sm[0];
        g_csum[side][b][r] = ss[0];
        g_cmean[side][b][r] = ss[0] / fmaxf(g_len[1 - side][b], EPSF);
    }
}

// ---------------- K5: attentive mean + max, 16 rows/block, coalesced ----------
// grid (16, BB, 2); block 128
__global__ void __launch_bounds__(128) k_att(const int* mp, const int* mh) {
    int gq = blockIdx.x, b = blockIdx.y, side = blockIdx.z;
    int i0 = gq * 16, t = threadIdx.x;
    __shared__ float satt[SS][20];   // [j][r], pad 20 (16B-aligned rows)
    __shared__ float sbias[SS];
    const int* omsk = side ? mp : mh;
    for (int idx = t; idx < 16 * SS; idx += 128) {
        int r = idx >> 8, j = idx & 255;
        satt[j][r] = side ? g_cosT[b][i0 + r][j] : g_cos[b][i0 + r][j];
    }
    for (int j = t; j < SS; j += 128)
        sbias[j] = omsk[b * SS + j] ? 0.f : -NEGF;
    __syncthreads();
    if (t < HH) {
        const float* oc = &g_c[1 - side][b][0][0];
        float mean[16], vmax[16];
#pragma unroll
        for (int r = 0; r < 16; r++) { mean[r] = 0.f; vmax[r] = -NEGF; }
        for (int j = 0; j < SS; j++) {
            float v = oc[j * HH + t];
            float bj = sbias[j];
            float4 a0 = *(const float4*)&satt[j][0];
            float4 a1 = *(const float4*)&satt[j][4];
            float4 a2 = *(const float4*)&satt[j][8];
            float4 a3 = *(const float4*)&satt[j][12];
            float a[16] = {a0.x, a0.y, a0.z, a0.w, a1.x, a1.y, a1.z, a1.w,
                           a2.x, a2.y, a2.z, a2.w, a3.x, a3.y, a3.z, a3.w};
#pragma unroll
            for (int r = 0; r < 16; r++) {
                mean[r] = fmaf(a[r], v, mean[r]);
                vmax[r] = fmaxf(vmax[r], fmaf(a[r], v, bj));
            }
        }
#pragma unroll
        for (int r = 0; r < 16; r++) {
            int i = i0 + r;
            float denom = fmaxf(g_csum[side][b][i], EPSF);
            g_attmean[side][b][i][t] = mean[r] / denom;
            g_attmax[side][b][i][t] = vmax[r];
        }
    }
}

// ---------------- K6: maxpool multi-perspective GEMM (f32x2, dup-B) -----------
// grid (PP, BB, 4); block 128 = tx8 x ty16; i-tile 64, 16 j-tiles of 16
__global__ void __launch_bounds__(128) k_maxpool(const int* mp, const int* mh) {
    int p = blockIdx.x, b = blockIdx.y, ibl = blockIdx.z, i0 = ibl * 64;
    int t = threadIdx.x, tx = t & 7, ty = t >> 3;
    __shared__ ull sA[HH][34];
    __shared__ ull sBd[HH][18];
    __shared__ float sRedM[16][16], sRedS[16][16];
    __shared__ float sbJ[16], siJ[16];

    for (int idx = t; idx < HH * 32; idx += 128) {
        int h = idx >> 5, ip = idx & 31;
        float2 v = *(const float2*)&g_cT[0][b][h][i0 + 2 * ip];
        float w = g_w2[1][p][h];
        sA[h][ip] = pk2(v.x * w, v.y * w);
    }
    float invp[4], biasI[4], pmax[4], psum[4];
#pragma unroll
    for (int r = 0; r < 4; r++) {
        int i = i0 + ty * 4 + r;
        float n = g_npw[0][b][i][PP + p];
        int mi = mp[b * SS + i];
        invp[r] = (mi && n > 0.f) ? 1.f / n : 0.f;
        biasI[r] = mi ? 0.f : -NEGF;
        pmax[r] = -NEGF; psum[r] = 0.f;
    }
    float len_h = g_len[1][b];

    for (int jt = 0; jt < 16; jt++) {
        int j0 = jt * 16;
        __syncthreads();
        for (int idx = t; idx < HH * 16; idx += 128) {
            int h = idx >> 4, j = idx & 15;
            float v = g_cT[1][b][h][j0 + j];
            sBd[h][j] = pk2(v, v);
        }
        if (t < 16) {
            int j = j0 + t;
            float n = g_npw[1][b][j][PP + p];
            int mj = mh[b * SS + j];
            siJ[t] = (mj && n > 0.f) ? 1.f / n : 0.f;
            sbJ[t] = mj ? 0.f : -NEGF;
        }
        __syncthreads();

        ull acc[2][2] = {0, 0, 0, 0};
#pragma unroll 4
        for (int h = 0; h < HH; h++) {
            ulonglong2 a = *(const ulonglong2*)&sA[h][ty * 2];
            ulonglong2 bd = *(const ulonglong2*)&sBd[h][tx * 2];
            acc[0][0] = fma2_(a.x, bd.x, acc[0][0]);
            acc[0][1] = fma2_(a.y, bd.x, acc[0][1]);
            acc[1][0] = fma2_(a.x, bd.y, acc[1][0]);
            acc[1][1] = fma2_(a.y, bd.y, acc[1][1]);
        }
#pragma unroll
        for (int jj = 0; jj < 2; jj++) {
            int jl = tx * 2 + jj;
            float sj = siJ[jl], bj = sbJ[jl];
            float cm = -NEGF, cs = 0.f;
#pragma unroll
            for (int rp = 0; rp < 2; rp++) {
                float dl, dh; unpk2(acc[jj][rp], dl, dh);
                int r0 = rp * 2, r1 = rp * 2 + 1;
                float v0 = dl * sj; psum[r0] += v0; pmax[r0] = fmaxf(pmax[r0], v0 + bj);
                float v1 = dh * sj; psum[r1] += v1; pmax[r1] = fmaxf(pmax[r1], v1 + bj);
                float u0 = dl * invp[r0]; cs += u0; cm = fmaxf(cm, u0 + biasI[r0]);
                float u1 = dh * invp[r1]; cs += u1; cm = fmaxf(cm, u1 + biasI[r1]);
            }
            sRedM[ty][jl] = cm; sRedS[ty][jl] = cs;
        }
        __syncthreads();
        if (t < 16) {
            float m = -NEGF, s = 0.f;
#pragma unroll
            for (int k = 0; k < 16; k++) { m = fmaxf(m, sRedM[k][t]); s += sRedS[k][t]; }
            g_colmax[ibl][b][p][j0 + t] = m;
            g_colsum[ibl][b][p][j0 + t] = s;
        }
    }
#pragma unroll
    for (int r = 0; r < 4; r++) {
        float m = pmax[r], s = psum[r];
        for (int o = 4; o; o >>= 1) {
            m = fmaxf(m, __shfl_xor_sync(0xffffffffu, m, o));
            s += __shfl_xor_sync(0xffffffffu, s, o);
        }
        if (tx == 0) {
            int i = i0 + ty * 4 + r;
            g_mpmax[0][b][i][p] = m * invp[r];
            g_mpmean[0][b][i][p] = s * invp[r] / fmaxf(len_h, EPSF);
        }
    }
}

// ---------------- K6b: combine column partials --------------------------------
__global__ void k_mpc(const int* mh) {
    int p = blockIdx.x, b = blockIdx.y, j = threadIdx.x;
    float m = -NEGF, s = 0.f;
#pragma unroll
    for (int k = 0; k < 4; k++) {
        m = fmaxf(m, g_colmax[k][b][p][j]);
        s += g_colsum[k][b][p][j];
    }
    float n = g_npw[1][b][j][PP + p];
    int mj = mh[b * SS + j];
    float inv = (mj && n > 0.f) ? 1.f / n : 0.f;
    g_mpmax[1][b][j][p] = m * inv;
    g_mpmean[1][b][j][p] = s * inv / fmaxf(g_len[0][b], EPSF);
}

// ---------------- K7: assemble 105 outputs (W2 staged in smem) ----------------
__global__ void __launch_bounds__(128) k_final(float* out) {
    int side = blockIdx.z, b = blockIdx.y, i = blockIdx.x, t = threadIdx.x;
    __shared__ float sW[60][101];  // 0-19: w_full, 20-39: w_att, 40-59: w_maxatt
    __shared__ float sx[HH], sL[HH], sva[HH], svm[HH], sred[105];
    const float* w0 = &g_w2[0][0][0];
    const float* w2 = &g_w2[2][0][0];
    const float* w3 = &g_w2[3][0][0];
    for (int idx = t; idx < 20 * HH; idx += 128) {
        int pr = idx / HH, h = idx % HH;
        sW[pr][h] = w0[idx];
        sW[20 + pr][h] = w2[idx];
        sW[40 + pr][h] = w3[idx];
    }
    if (t < HH) {
        sx[t] = g_c[side][b][i][t];
        sL[t] = g_last[1 - side][b][t];
        sva[t] = g_attmean[side][b][i][t];
        svm[t] = g_attmax[side][b][i][t];
    }
    __syncthreads();
    if (t < 105) {
        float s = 0.f;
        if (t == 0)      { for (int h = 0; h < HH; h++) s += sx[h] * sL[h]; }
        else if (t == 1) { for (int h = 0; h < HH; h++) s += sx[h] * sva[h]; }
        else if (t == 2) { for (int h = 0; h < HH; h++) s += sx[h] * svm[h]; }
        else if (t == 3) { for (int h = 0; h < HH; h++) s += sva[h] * sva[h]; }
        else if (t == 4) { for (int h = 0; h < HH; h++) s += svm[h] * svm[h]; }
        else if (t < 25) { int p = t - 5;  for (int h = 0; h < HH; h++) s += sW[p][h] * sx[h] * sL[h]; }
        else if (t < 45) { int p = t - 25; for (int h = 0; h < HH; h++) s += sW[20 + p][h] * sx[h] * sva[h]; }
        else if (t < 65) { int p = t - 45; for (int h = 0; h < HH; h++) s += sW[20 + p][h] * sva[h] * sva[h]; }
        else if (t < 85) { int p = t - 65; for (int h = 0; h < HH; h++) s += sW[40 + p][h] * sx[h] * svm[h]; }
        else             { int p = t - 85; for (int h = 0; h < HH; h++) s += sW[40 + p][h] * svm[h] * svm[h]; }
        sred[t] = s;
    }
    __syncthreads();
    if (t < 105) {
        float np = g_norm[side][b][i];
        float o;
        if (t == 0)      o = g_cmax[side][b][i];
        else if (t == 1) o = g_cmean[side][b][i];
        else if (t == 2) o = sred[0] / (fmaxf(np, EPSF) * fmaxf(g_nlast[1 - side][b], EPSF));
        else if (t < 23) {
            int p = t - 3;
            o = sred[5 + p] / (fmaxf(g_npw[side][b][i][p], EPSF) * fmaxf(g_nlastw[1 - side][b][p], EPSF));
        }
        else if (t < 43) o = g_mpmax[side][b][i][t - 23];
        else if (t < 63) o = g_mpmean[side][b][i][t - 43];
        else if (t == 63) o = sred[1] / (fmaxf(np, EPSF) * fmaxf(sqrtf(sred[3]), EPSF));
        else if (t < 84) {
            int p = t - 64;
            o = sred[25 + p] / (fmaxf(g_npw[side][b][i][2 * PP + p], EPSF) * fmaxf(sqrtf(sred[45 + p]), EPSF));
        }
        else if (t == 84) o = sred[2] / (fmaxf(np, EPSF) * fmaxf(sqrtf(sred[4]), EPSF));
        else {
            int p = t - 85;
            o = sred[65 + p] / (fmaxf(g_npw[side][b][i][3 * PP + p], EPSF) * fmaxf(sqrtf(sred[85 + p]), EPSF));
        }
        out[((size_t)(side * BB + b) * SS + i) * 105 + t] = o;
    }
}

// ---------------- launch ------------------------------------------------------
extern "C" void kernel_launch(void* const* d_in, const int* in_sizes, int n_in,
                              void* d_out, int out_size) {
    const float* ctx_p = (const float*)d_in[0];
    const int*   mp    = (const int*)d_in[1];
    const float* ctx_h = (const float*)d_in[2];
    const int*   mh    = (const int*)d_in[3];
    const float* wf    = (const float*)d_in[4];
    const float* wm    = (const float*)d_in[5];
    const float* wa    = (const float*)d_in[6];
    const float* wx    = (const float*)d_in[7];
    float* out = (float*)d_out;

    k_w2<<<4, 256>>>(wf, wm, wa, wx);
    k_prep1<<<dim3(BB * SS, 2), 128>>>(ctx_p, mp, ctx_h, mh);
    k_prep2<<<dim3(16, BB, 2), 128>>>();
    k_last<<<dim3(BB, 2), 128>>>(mp, mh);
    k_cos<<<dim3(BB, 4, 16), 128>>>();
    k_rowred<<<dim3(SS, BB, 2), 256>>>(mp, mh);
    k_att<<<dim3(16, BB, 2), 128>>>(mp, mh);
    k_maxpool<<<dim3(PP, BB, 4), 128>>>(mp, mh);
    k_mpc<<<dim3(PP, BB), 256>>>(mh);
    k_final<<<dim3(SS, BB, 2), 128>>>(out);
}